// round 10
// baseline (speedup 1.0000x reference)
#include <cuda_runtime.h>

#define EPS 1e-4f
#define FRAMES 4000
#define NF4 1000            // 4000 floats = 1000 float4
#define T 256               // 8 warps; each warp owns 128 contiguous float4

__global__ __launch_bounds__(T) void cumnorm_kernel(const float4* __restrict__ x,
                                                    float4* __restrict__ out) {
    __shared__ float ws1[8];
    __shared__ float ws2[8];

    const int tid = threadIdx.x;
    const int lane = tid & 31;
    const int wid = tid >> 5;
    const long long rowbase = (long long)blockIdx.x * NF4;
    const int wb = wid * 128;            // warp's first float4 index

    // 1) fully coalesced load: lane l, reg k -> float4 index wb + 32k + l.
    //    Element order over (k major, l minor) is the linear frame order.
    float4 v[4];
#pragma unroll
    for (int k = 0; k < 4; k++) {
        int idx = wb + 32 * k + lane;
        float4 a = make_float4(0.f, 0.f, 0.f, 0.f);
        if (idx < NF4) a = __ldcs(&x[rowbase + idx]);
        v[k] = a;
    }

    // 2) 4 warp-level inclusive shfl-scans (one per k) with sequential carry.
    //    e1[k]/e2[k] = exclusive prefix (sum, sumsq) within the warp segment
    //    for this lane's float4 at reg k.
    float e1[4], e2[4];
    float c1 = 0.f, c2 = 0.f;
#pragma unroll
    for (int k = 0; k < 4; k++) {
        float4 a = v[k];
        float t1 = (a.x + a.y) + (a.z + a.w);
        float t2 = fmaf(a.x, a.x, fmaf(a.y, a.y, fmaf(a.z, a.z, a.w * a.w)));
        float i1 = t1, i2 = t2;
#pragma unroll
        for (int o = 1; o < 32; o <<= 1) {
            float u1 = __shfl_up_sync(0xffffffffu, i1, o);
            float u2 = __shfl_up_sync(0xffffffffu, i2, o);
            if (lane >= o) { i1 += u1; i2 += u2; }
        }
        e1[k] = c1 + (i1 - t1);
        e2[k] = c2 + (i2 - t2);
        c1 += __shfl_sync(0xffffffffu, i1, 31);   // warp-segment running total
        c2 += __shfl_sync(0xffffffffu, i2, 31);
    }

    // 3) cross-warp carry (8 warp totals via smem)
    if (lane == 0) { ws1[wid] = c1; ws2[wid] = c2; }
    __syncthreads();
    float wp1 = 0.f, wp2 = 0.f;
#pragma unroll
    for (int w = 0; w < 8; w++) {
        if (w < wid) { wp1 += ws1[w]; wp2 += ws2[w]; }
    }

    // 4) causal normalization, division-free:
    //    (x - r1/c) / sqrt(r2/c - (r1/c)^2 + eps)
    //  = (c*x - r1) * rsqrt(c*r2 - r1^2 + eps*c^2)
    //    then fully coalesced streaming store.
#pragma unroll
    for (int k = 0; k < 4; k++) {
        int idx = wb + 32 * k + lane;
        float r1 = wp1 + e1[k];
        float r2 = wp2 + e2[k];
        float c = (float)(4 * idx);
        float4 a = v[k];
        float4 o;
        {
            c += 1.f; r1 += a.x; r2 = fmaf(a.x, a.x, r2);
            float S = fmaf(EPS * c, c, fmaf(c, r2, -r1 * r1));
            o.x = fmaf(c, a.x, -r1) * rsqrtf(S);
        }
        {
            c += 1.f; r1 += a.y; r2 = fmaf(a.y, a.y, r2);
            float S = fmaf(EPS * c, c, fmaf(c, r2, -r1 * r1));
            o.y = fmaf(c, a.y, -r1) * rsqrtf(S);
        }
        {
            c += 1.f; r1 += a.z; r2 = fmaf(a.z, a.z, r2);
            float S = fmaf(EPS * c, c, fmaf(c, r2, -r1 * r1));
            o.z = fmaf(c, a.z, -r1) * rsqrtf(S);
        }
        {
            c += 1.f; r1 += a.w; r2 = fmaf(a.w, a.w, r2);
            float S = fmaf(EPS * c, c, fmaf(c, r2, -r1 * r1));
            o.w = fmaf(c, a.w, -r1) * rsqrtf(S);
        }
        if (idx < NF4) __stcs(&out[rowbase + idx], o);
    }
}

extern "C" void kernel_launch(void* const* d_in, const int* in_sizes, int n_in,
                              void* d_out, int out_size) {
    const float4* x = (const float4*)d_in[0];
    float4* out = (float4*)d_out;
    const int rows = in_sizes[0] / FRAMES;   // 32*512 = 16384
    cumnorm_kernel<<<rows, T>>>(x, out);
}

// round 11
// speedup vs baseline: 1.5719x; 1.5719x over previous
#include <cuda_runtime.h>

#define EPS 1e-4f
#define FRAMES 4000
#define NF4 1000            // 4000 floats = 1000 float4 (padded to 1024 positions)
#define T 256               // 8 warps; warp w owns float4 positions [128w, 128w+128)

// XOR swizzle at float4 granularity (bijective on [0,512) float4 slots).
__device__ __forceinline__ int swz4(int q) { return q ^ ((q >> 3) & 7); }

__global__ __launch_bounds__(T) void cumnorm_kernel(const float4* __restrict__ x,
                                                    float4* __restrict__ out) {
    __shared__ float4 bufA[512];    // (t1,t2) totals: one float2 per float4-position
    __shared__ float4 bufB[512];    // exclusive (sum, sumsq) prefixes, float2/pos
    __shared__ float ws1[8];
    __shared__ float ws2[8];

    const int tid = threadIdx.x;
    const int lane = tid & 31;
    const int wid = tid >> 5;
    const long long rowbase = (long long)blockIdx.x * NF4;
    const int wb = wid * 128;       // warp's first float4 position

    // 1) fully coalesced load: lane l, reg k -> float4 position wb + 32k + l
    float4 v[4];
#pragma unroll
    for (int k = 0; k < 4; k++) {
        int idx = wb + 32 * k + lane;
        float4 a = make_float4(0.f, 0.f, 0.f, 0.f);
        if (idx < NF4) a = __ldcs(&x[rowbase + idx]);
        v[k] = a;
    }

    // 2) per-float4 totals -> bufA (float2 at swizzled position), coalesced STS.64
    float2* A2 = (float2*)bufA;
#pragma unroll
    for (int k = 0; k < 4; k++) {
        float4 a = v[k];
        float t1 = (a.x + a.y) + (a.z + a.w);
        float t2 = fmaf(a.x, a.x, fmaf(a.y, a.y, fmaf(a.z, a.z, a.w * a.w)));
        int p = wb + 32 * k + lane;
        int sp = (swz4(p >> 1) << 1) | (p & 1);
        A2[sp] = make_float2(t1, t2);
    }
    __syncthreads();

    // 3) thread t owns scan-chunk positions 4t..4t+3 (contiguous): 2 LDS.128
    float4 c0 = bufA[swz4(2 * tid)];        // (t1,t2) for p=4t and 4t+1
    float4 c1 = bufA[swz4(2 * tid + 1)];    // (t1,t2) for p=4t+2 and 4t+3
    float u1 = (c0.x + c0.z) + (c1.x + c1.z);
    float u2 = (c0.y + c0.w) + (c1.y + c1.w);

    // single warp shfl-scan over chunk totals (warp segment == data segment)
    float i1 = u1, i2 = u2;
#pragma unroll
    for (int o = 1; o < 32; o <<= 1) {
        float s1 = __shfl_up_sync(0xffffffffu, i1, o);
        float s2 = __shfl_up_sync(0xffffffffu, i2, o);
        if (lane >= o) { i1 += s1; i2 += s2; }
    }
    if (lane == 31) { ws1[wid] = i1; ws2[wid] = i2; }

    // within-warp-segment exclusive prefixes for the 4 chunk positions
    float X1 = i1 - u1, X2 = i2 - u2;
    float e1_1 = X1 + c0.x,   e2_1 = X2 + c0.y;
    float e1_2 = e1_1 + c0.z, e2_2 = e2_1 + c0.w;
    float e1_3 = e1_2 + c1.x, e2_3 = e2_2 + c1.y;
    bufB[swz4(2 * tid)]     = make_float4(X1,  X2,  e1_1, e2_1);
    bufB[swz4(2 * tid + 1)] = make_float4(e1_2, e2_2, e1_3, e2_3);
    __syncthreads();

    // 4) cross-warp carry
    float wp1 = 0.f, wp2 = 0.f;
#pragma unroll
    for (int w = 0; w < 8; w++) {
        if (w < wid) { wp1 += ws1[w]; wp2 += ws2[w]; }
    }

    // 5) read own prefixes coalesced (LDS.64), normalize division-free:
    //    (x - r1/c)/sqrt(r2/c - (r1/c)^2 + eps) = (c*x - r1)*rsqrt(c*r2 - r1^2 + eps*c^2)
    float2* B2 = (float2*)bufB;
#pragma unroll
    for (int k = 0; k < 4; k++) {
        int idx = wb + 32 * k + lane;
        int sp = (swz4(idx >> 1) << 1) | (idx & 1);
        float2 E = B2[sp];
        float r1 = wp1 + E.x;
        float r2 = wp2 + E.y;
        float c = (float)(4 * idx);
        float4 a = v[k];
        float4 o;
        {
            c += 1.f; r1 += a.x; r2 = fmaf(a.x, a.x, r2);
            float S = fmaf(EPS * c, c, fmaf(c, r2, -r1 * r1));
            o.x = fmaf(c, a.x, -r1) * rsqrtf(S);
        }
        {
            c += 1.f; r1 += a.y; r2 = fmaf(a.y, a.y, r2);
            float S = fmaf(EPS * c, c, fmaf(c, r2, -r1 * r1));
            o.y = fmaf(c, a.y, -r1) * rsqrtf(S);
        }
        {
            c += 1.f; r1 += a.z; r2 = fmaf(a.z, a.z, r2);
            float S = fmaf(EPS * c, c, fmaf(c, r2, -r1 * r1));
            o.z = fmaf(c, a.z, -r1) * rsqrtf(S);
        }
        {
            c += 1.f; r1 += a.w; r2 = fmaf(a.w, a.w, r2);
            float S = fmaf(EPS * c, c, fmaf(c, r2, -r1 * r1));
            o.w = fmaf(c, a.w, -r1) * rsqrtf(S);
        }
        if (idx < NF4) __stcs(&out[rowbase + idx], o);
    }
}

extern "C" void kernel_launch(void* const* d_in, const int* in_sizes, int n_in,
                              void* d_out, int out_size) {
    const float4* x = (const float4*)d_in[0];
    float4* out = (float4*)d_out;
    const int rows = in_sizes[0] / FRAMES;   // 32*512 = 16384
    cumnorm_kernel<<<rows, T>>>(x, out);
}